// round 12
// baseline (speedup 1.0000x reference)
#include <cuda_runtime.h>
#include <cstdint>

#define MAXN 50000
#define F0 64
#define F1 64
#define F2 32
#define F3 16

#define SLOT 64   // fixed CSR slot per node; Poisson(16) => P(deg>=64) ~ 2e-18

// Scratch (device globals: no allocation allowed).
// INVARIANT: g_deg == 0 at kernel_launch entry. Zero-initialized at module
// load; each pull kernel restores its layer's range inline before finishing,
// so graph replays always enter clean.
__device__ int   g_deg[3 * MAXN];
__device__ int   g_csr[3 * MAXN * SLOT];   // fixed-stride per-destination lists
__device__ float g_h1[MAXN * 64];          // layer-1: x@W1, then prescaled by dinv1
__device__ float g_h2[MAXN * 32];          // layer-2 h' = dinv2 * (x2@W2)
__device__ float g_h3[MAXN * 16];          // layer-3 h' = dinv3 * (x3@W3)

// ---------------------------------------------------------------------------
// mega1: role-split blocks.
//   blocks [0, gemm_blocks)    : h1 = x @ W1 (f32x2 packed FMA, unscaled)
//   blocks [gemm_blocks, ...)  : fused count+place for ALL 3 layers, 4 edges/thread
// ---------------------------------------------------------------------------
__global__ void mega1_kernel(const float* __restrict__ x,
                             const float* __restrict__ W1,
                             float* __restrict__ h1,
                             const int* __restrict__ s1, const int* __restrict__ d1, int e1,
                             const int* __restrict__ s2, const int* __restrict__ d2, int e2,
                             const int* __restrict__ s3, const int* __restrict__ d3, int e3,
                             int n, int gemm_blocks) {
    __shared__ float sW[F0 * F1];
    __shared__ float sx[64][F0 + 1];

    int tid = threadIdx.x;

    if ((int)blockIdx.x < gemm_blocks) {
        // ----- GEMM role -----
        constexpr int CH  = F1 / 4;   // 16
        constexpr int CP  = CH / 2;   // 8
        constexpr int CH4 = CH / 4;   // 4

        for (int i = tid; i < F0 * F1 / 4; i += 256)
            ((float4*)sW)[i] = ((const float4*)W1)[i];

        int node0 = blockIdx.x * 64;
        for (int i = tid; i < 64 * F0; i += 256) {
            int r = i / F0, c = i % F0;
            int nd = node0 + r;
            sx[r][c] = (nd < n) ? x[(size_t)nd * F0 + c] : 0.0f;
        }
        __syncthreads();

        int r = tid >> 2, t = tid & 3;
        int nd = node0 + r;

        unsigned long long acc2[CP];
#pragma unroll
        for (int i = 0; i < CP; i++) acc2[i] = 0ull;

#pragma unroll
        for (int k = 0; k < F0; k++) {
            float xv = sx[r][k];
            unsigned xu = __float_as_uint(xv);
            unsigned long long xv2;
            asm("mov.b64 %0, {%1, %1};" : "=l"(xv2) : "r"(xu));
            const ulonglong2* wrow = (const ulonglong2*)(sW + k * F1) + t * CH4;
#pragma unroll
            for (int c = 0; c < CH4; c++) {
                ulonglong2 wv = wrow[c];
                asm("fma.rn.f32x2 %0, %1, %2, %0;" : "+l"(acc2[2 * c + 0]) : "l"(xv2), "l"(wv.x));
                asm("fma.rn.f32x2 %0, %1, %2, %0;" : "+l"(acc2[2 * c + 1]) : "l"(xv2), "l"(wv.y));
            }
        }

        if (nd < n) {
            float4* out = (float4*)(h1 + (size_t)nd * F1) + t * CH4;
#pragma unroll
            for (int c = 0; c < CH4; c++) {
                float a0, a1, a2, a3;
                asm("mov.b64 {%0, %1}, %2;" : "=f"(a0), "=f"(a1) : "l"(acc2[2 * c + 0]));
                asm("mov.b64 {%0, %1}, %2;" : "=f"(a2), "=f"(a3) : "l"(acc2[2 * c + 1]));
                out[c] = make_float4(a0, a1, a2, a3);
            }
        }
    } else {
        // ----- edge role: count+place for all 3 layers -----
        int t4 = ((blockIdx.x - gemm_blocks) * blockDim.x + tid) * 4;
        const int* src; const int* dst; int e, gbase, i;
        if (t4 < e1)           { src = s1; dst = d1; e = e1; gbase = 0;     i = t4; }
        else if (t4 < e1 + e2) { src = s2; dst = d2; e = e2; gbase = n;     i = t4 - e1; }
        else                   { src = s3; dst = d3; e = e3; gbase = 2 * n; i = t4 - e1 - e2; }
        if (i >= e) return;

        if (i + 3 < e) {
            int4 d4 = *reinterpret_cast<const int4*>(dst + i);
            int4 s4 = *reinterpret_cast<const int4*>(src + i);
            int da = gbase + d4.x, db = gbase + d4.y;
            int dc = gbase + d4.z, dd = gbase + d4.w;
            int pa = atomicAdd(&g_deg[da], 1);
            int pb = atomicAdd(&g_deg[db], 1);
            int pc = atomicAdd(&g_deg[dc], 1);
            int pd = atomicAdd(&g_deg[dd], 1);
            g_csr[(da << 6) + pa] = s4.x;
            g_csr[(db << 6) + pb] = s4.y;
            g_csr[(dc << 6) + pc] = s4.z;
            g_csr[(dd << 6) + pd] = s4.w;
        } else {
            for (; i < e; i++) {
                int d = gbase + dst[i];
                int pos = atomicAdd(&g_deg[d], 1);
                g_csr[(d << 6) + pos] = src[i];
            }
        }
    }
}

// ---------------------------------------------------------------------------
// scale1: h1[node,:] *= dinv1[node]  (prescale so pull1 gathers need no deg)
// ---------------------------------------------------------------------------
__global__ void scale1_kernel(float* __restrict__ h1,
                              const int* __restrict__ deg1, int n) {
    int i = blockIdx.x * blockDim.x + threadIdx.x;   // over n*16 float4s
    if (i < n * 16) {
        int node = i >> 4;
        float di = rsqrtf((float)deg1[node] + 1.0f);
        float4 v = ((float4*)h1)[i];
        v.x *= di; v.y *= di; v.z *= di; v.w *= di;
        ((float4*)h1)[i] = v;
    }
}

// ---------------------------------------------------------------------------
// Fused pull(layer1) + gemm2. 16 nodes/block, TG=16. h1 prescaled.
// Pure-add gathers, int4 csr loads. Restores deg1[node]=0 inline.
// h2 written PRE-SCALED by dinv2.
// ---------------------------------------------------------------------------
__global__ void pull1_gemm2_kernel(const float* __restrict__ h1,
                                   const float* __restrict__ b1,
                                   const float* __restrict__ W2,
                                   float* __restrict__ h2,
                                   int* __restrict__ deg1,
                                   const int* __restrict__ deg2, int n) {
    __shared__ float sx2[16][F1 + 1];
    __shared__ float sW2[F1 * F2];      // 8KB

    int tid = threadIdx.x;
    for (int i = tid; i < F1 * F2 / 4; i += 256)
        ((float4*)sW2)[i] = ((const float4*)W2)[i];

    int node = blockIdx.x * 16 + (tid >> 4);
    int f4   = tid & 15;

    if (node < n) {
        const float4* hp = (const float4*)h1;
        int dg = deg1[node];
        if (f4 == 0) deg1[node] = 0;     // sole reader; restore invariant
        float di = rsqrtf((float)dg + 1.0f);
        float4 acc = hp[node * 16 + f4]; // self (prescaled)

        int idx = node << 6;
        int end = idx + dg;
        const int* __restrict__ csr = g_csr;

        for (; idx + 3 < end; idx += 4) {
            int4 s4 = *reinterpret_cast<const int4*>(csr + idx);
            float4 va = hp[s4.x * 16 + f4];
            float4 vb = hp[s4.y * 16 + f4];
            float4 vc = hp[s4.z * 16 + f4];
            float4 vd = hp[s4.w * 16 + f4];
            acc.x += (va.x + vb.x) + (vc.x + vd.x);
            acc.y += (va.y + vb.y) + (vc.y + vd.y);
            acc.z += (va.z + vb.z) + (vc.z + vd.z);
            acc.w += (va.w + vb.w) + (vc.w + vd.w);
        }
        for (; idx < end; idx++) {
            int sa = csr[idx];
            float4 va = hp[sa * 16 + f4];
            acc.x += va.x; acc.y += va.y; acc.z += va.z; acc.w += va.w;
        }

        float4 bb = *(const float4*)(b1 + f4 * 4);
        int r = tid >> 4;
        sx2[r][f4 * 4 + 0] = fmaxf(fmaf(di, acc.x, bb.x), 0.0f);
        sx2[r][f4 * 4 + 1] = fmaxf(fmaf(di, acc.y, bb.y), 0.0f);
        sx2[r][f4 * 4 + 2] = fmaxf(fmaf(di, acc.z, bb.z), 0.0f);
        sx2[r][f4 * 4 + 3] = fmaxf(fmaf(di, acc.w, bb.w), 0.0f);
    }
    __syncthreads();

    // gemm2: h2 = dinv2 * (x2 @ W2)
    int r  = tid >> 4;
    int j0 = tid & 15;
    int nd = blockIdx.x * 16 + r;
    if (nd < n) {
        float a0 = 0.0f, a1 = 0.0f;
#pragma unroll
        for (int k = 0; k < F1; k++) {
            float xv = sx2[r][k];
            a0 = fmaf(xv, sW2[k * F2 + j0],      a0);
            a1 = fmaf(xv, sW2[k * F2 + j0 + 16], a1);
        }
        float d2 = rsqrtf((float)deg2[nd] + 1.0f);
        h2[nd * F2 + j0]      = d2 * a0;
        h2[nd * F2 + j0 + 16] = d2 * a1;
    }
}

// ---------------------------------------------------------------------------
// Fused pull(layer2) + gemm3. 32 nodes/block, TG=8. h2 prescaled.
// Restores deg2[node]=0 inline.
// ---------------------------------------------------------------------------
__global__ void pull2_gemm3_kernel(const float* __restrict__ h2,
                                   const float* __restrict__ b2,
                                   const float* __restrict__ W3,
                                   float* __restrict__ h3,
                                   int* __restrict__ deg2,
                                   const int* __restrict__ deg3, int n) {
    __shared__ float sx3[32][F2 + 1];
    __shared__ float sW3[F2 * F3];      // 2KB

    int tid = threadIdx.x;
    for (int i = tid; i < F2 * F3 / 4; i += 256)
        ((float4*)sW3)[i] = ((const float4*)W3)[i];

    int node = blockIdx.x * 32 + (tid >> 3);
    int f4   = tid & 7;

    if (node < n) {
        const float4* hp = (const float4*)h2;
        int dg = deg2[node];
        if (f4 == 0) deg2[node] = 0;     // restore invariant
        float di = rsqrtf((float)dg + 1.0f);
        float4 acc = hp[node * 8 + f4];  // self (prescaled)

        int idx = (MAXN << 6) + (node << 6);
        int end = idx + dg;
        const int* __restrict__ csr = g_csr;

        for (; idx + 3 < end; idx += 4) {
            int4 s4 = *reinterpret_cast<const int4*>(csr + idx);
            float4 va = hp[s4.x * 8 + f4];
            float4 vb = hp[s4.y * 8 + f4];
            float4 vc = hp[s4.z * 8 + f4];
            float4 vd = hp[s4.w * 8 + f4];
            acc.x += (va.x + vb.x) + (vc.x + vd.x);
            acc.y += (va.y + vb.y) + (vc.y + vd.y);
            acc.z += (va.z + vb.z) + (vc.z + vd.z);
            acc.w += (va.w + vb.w) + (vc.w + vd.w);
        }
        for (; idx < end; idx++) {
            int sa = csr[idx];
            float4 va = hp[sa * 8 + f4];
            acc.x += va.x; acc.y += va.y; acc.z += va.z; acc.w += va.w;
        }

        float4 bb = *(const float4*)(b2 + f4 * 4);
        int r = tid >> 3;
        sx3[r][f4 * 4 + 0] = fmaxf(fmaf(di, acc.x, bb.x), 0.0f);
        sx3[r][f4 * 4 + 1] = fmaxf(fmaf(di, acc.y, bb.y), 0.0f);
        sx3[r][f4 * 4 + 2] = fmaxf(fmaf(di, acc.z, bb.z), 0.0f);
        sx3[r][f4 * 4 + 3] = fmaxf(fmaf(di, acc.w, bb.w), 0.0f);
    }
    __syncthreads();

    // gemm3: h3 = dinv3 * (x3 @ W3)
    int r  = tid >> 3;
    int j0 = tid & 7;
    int nd = blockIdx.x * 32 + r;
    if (nd < n) {
        float a0 = 0.0f, a1 = 0.0f;
#pragma unroll
        for (int k = 0; k < F2; k++) {
            float xv = sx3[r][k];
            a0 = fmaf(xv, sW3[k * F3 + j0],     a0);
            a1 = fmaf(xv, sW3[k * F3 + j0 + 8], a1);
        }
        float d3 = rsqrtf((float)deg3[nd] + 1.0f);
        h3[nd * F3 + j0]     = d3 * a0;
        h3[nd * F3 + j0 + 8] = d3 * a1;
    }
}

// ---------------------------------------------------------------------------
// Final pull (layer 3). h3 prescaled. Restores deg3[node]=0 inline.
// ---------------------------------------------------------------------------
__global__ void pull3_kernel(const float* __restrict__ h3,
                             const float* __restrict__ b3,
                             float* __restrict__ y,
                             int* __restrict__ deg3, int n) {
    constexpr int TG = F3 / 4;   // 4
    int t = blockIdx.x * blockDim.x + threadIdx.x;
    int node = t / TG;
    int f4   = t % TG;
    if (node >= n) return;

    const float4* hp = (const float4*)h3;
    int dg = deg3[node];
    if (f4 == 0) deg3[node] = 0;         // restore invariant
    float4 acc = hp[node * TG + f4];

    int idx = (2 * MAXN << 6) + (node << 6);
    int end = idx + dg;
    const int* __restrict__ csr = g_csr;

    for (; idx + 3 < end; idx += 4) {
        int4 s4 = *reinterpret_cast<const int4*>(csr + idx);
        float4 va = hp[s4.x * TG + f4];
        float4 vb = hp[s4.y * TG + f4];
        float4 vc = hp[s4.z * TG + f4];
        float4 vd = hp[s4.w * TG + f4];
        acc.x += (va.x + vb.x) + (vc.x + vd.x);
        acc.y += (va.y + vb.y) + (vc.y + vd.y);
        acc.z += (va.z + vb.z) + (vc.z + vd.z);
        acc.w += (va.w + vb.w) + (vc.w + vd.w);
    }
    for (; idx < end; idx++) {
        int sa = csr[idx];
        float4 va = hp[sa * TG + f4];
        acc.x += va.x; acc.y += va.y; acc.z += va.z; acc.w += va.w;
    }

    float di = rsqrtf((float)dg + 1.0f);
    float4 bb = *(const float4*)(b3 + f4 * 4);
    float4 o;
    o.x = fmaxf(fmaf(di, acc.x, bb.x), 0.0f);
    o.y = fmaxf(fmaf(di, acc.y, bb.y), 0.0f);
    o.z = fmaxf(fmaf(di, acc.z, bb.z), 0.0f);
    o.w = fmaxf(fmaf(di, acc.w, bb.w), 0.0f);
    ((float4*)y)[node * TG + f4] = o;
}

// ---------------------------------------------------------------------------
extern "C" void kernel_launch(void* const* d_in, const int* in_sizes, int n_in,
                              void* d_out, int out_size) {
    const float* features = (const float*)d_in[0];
    const int*   ei1      = (const int*)  d_in[1];
    const int*   ei2      = (const int*)  d_in[2];
    const int*   ei3      = (const int*)  d_in[3];
    const float* W1       = (const float*)d_in[4];
    const float* b1       = (const float*)d_in[5];
    const float* W2       = (const float*)d_in[6];
    const float* b2       = (const float*)d_in[7];
    const float* W3       = (const float*)d_in[8];
    const float* b3       = (const float*)d_in[9];
    float* out = (float*)d_out;

    int n  = in_sizes[0] / F0;       // 50000
    int e1 = in_sizes[1] / 2;
    int e2 = in_sizes[2] / 2;
    int e3 = in_sizes[3] / 2;

    const int* s1 = ei1;  const int* d1 = ei1 + e1;
    const int* s2 = ei2;  const int* d2 = ei2 + e2;
    const int* s3 = ei3;  const int* d3 = ei3 + e3;

    float* h1 = nullptr;  cudaGetSymbolAddress((void**)&h1, g_h1);
    float* h2 = nullptr;  cudaGetSymbolAddress((void**)&h2, g_h2);
    float* h3 = nullptr;  cudaGetSymbolAddress((void**)&h3, g_h3);
    int*   deg = nullptr; cudaGetSymbolAddress((void**)&deg, g_deg);

    int gemm_blocks = (n + 63) / 64;                       // 782
    int edge_threads = (e1 + e2 + e3 + 3) / 4;             // 600000
    int edge_blocks  = (edge_threads + 255) / 256 + 1;     // +1: layer-boundary slack
    int total_blocks = gemm_blocks + edge_blocks;

    // Single stream, 5 kernel nodes, no events.
    mega1_kernel<<<total_blocks, 256>>>(features, W1, h1,
                                        s1, d1, e1, s2, d2, e2, s3, d3, e3,
                                        n, gemm_blocks);

    scale1_kernel<<<(n * 16 + 255) / 256, 256>>>(h1, deg, n);

    pull1_gemm2_kernel<<<(n + 15) / 16, 256>>>(h1, b1, W2, h2, deg, deg + n, n);

    pull2_gemm3_kernel<<<(n + 31) / 32, 256>>>(h2, b2, W3, h3, deg + n, deg + 2 * n, n);

    pull3_kernel<<<(n * (F3 / 4) + 255) / 256, 256>>>(h3, b3, out, deg + 2 * n, n);
}

// round 13
// speedup vs baseline: 1.0041x; 1.0041x over previous
#include <cuda_runtime.h>
#include <cstdint>

#define MAXN 50000
#define F0 64
#define F1 64
#define F2 32
#define F3 16

#define SLOT 64   // fixed CSR slot per node; Poisson(16) => P(deg>=64) ~ 2e-18

// Scratch (device globals: no allocation allowed).
// INVARIANT: g_deg == 0 at kernel_launch entry. Zero-initialized at module
// load; each pull kernel restores its layer's range inline before finishing,
// so graph replays always enter clean.
__device__ int   g_deg[3 * MAXN];
__device__ int   g_csr[3 * MAXN * SLOT];   // fixed-stride per-destination lists
__device__ float g_h1[MAXN * 64];          // layer-1: x@W1, prescaled by dinv1 (scale1)
__device__ float g_h2[MAXN * 32];          // layer-2 h' = dinv2 * (x2@W2)
__device__ float g_h3[MAXN * 16];          // layer-3 h' = dinv3 * (x3@W3)

// ---------------------------------------------------------------------------
// Fused count + place, 4 edges/thread (4 independent atomic->store chains).
// ---------------------------------------------------------------------------
__global__ void countplace_kernel(const int* __restrict__ src,
                                  const int* __restrict__ dst,
                                  int e, int gbase) {
    int i = (blockIdx.x * blockDim.x + threadIdx.x) * 4;
    if (i + 3 < e) {
        int4 d4 = *reinterpret_cast<const int4*>(dst + i);
        int4 s4 = *reinterpret_cast<const int4*>(src + i);
        int da = gbase + d4.x, db = gbase + d4.y;
        int dc = gbase + d4.z, dd = gbase + d4.w;
        int pa = atomicAdd(&g_deg[da], 1);
        int pb = atomicAdd(&g_deg[db], 1);
        int pc = atomicAdd(&g_deg[dc], 1);
        int pd = atomicAdd(&g_deg[dd], 1);
        g_csr[(da << 6) + pa] = s4.x;
        g_csr[(db << 6) + pb] = s4.y;
        g_csr[(dc << 6) + pc] = s4.z;
        g_csr[(dd << 6) + pd] = s4.w;
    } else {
        for (; i < e; i++) {
            int d = gbase + dst[i];
            int pos = atomicAdd(&g_deg[d], 1);
            g_csr[(d << 6) + pos] = src[i];
        }
    }
}

// Fused layers 2+3 variant (one launch on stream B).
__global__ void countplace23_kernel(const int* __restrict__ s2, const int* __restrict__ d2, int e2,
                                    const int* __restrict__ s3, const int* __restrict__ d3, int e3,
                                    int n) {
    int t4 = (blockIdx.x * blockDim.x + threadIdx.x) * 4;
    const int* src; const int* dst; int e, gbase, i;
    if (t4 < e2) { src = s2; dst = d2; e = e2; gbase = n;     i = t4; }
    else         { src = s3; dst = d3; e = e3; gbase = 2 * n; i = t4 - e2; }
    if (i >= e) return;
    if (i + 3 < e) {
        int4 dd4 = *reinterpret_cast<const int4*>(dst + i);
        int4 ss4 = *reinterpret_cast<const int4*>(src + i);
        int da = gbase + dd4.x, db = gbase + dd4.y;
        int dc = gbase + dd4.z, de = gbase + dd4.w;
        int pa = atomicAdd(&g_deg[da], 1);
        int pb = atomicAdd(&g_deg[db], 1);
        int pc = atomicAdd(&g_deg[dc], 1);
        int pd = atomicAdd(&g_deg[de], 1);
        g_csr[(da << 6) + pa] = ss4.x;
        g_csr[(db << 6) + pb] = ss4.y;
        g_csr[(dc << 6) + pc] = ss4.z;
        g_csr[(de << 6) + pd] = ss4.w;
    } else {
        for (; i < e; i++) {
            int d = gbase + dst[i];
            int pos = atomicAdd(&g_deg[d], 1);
            g_csr[(d << 6) + pos] = src[i];
        }
    }
}

// ---------------------------------------------------------------------------
// Layer-1 GEMM (f32x2 packed FMA), unscaled: h1 = x @ W1. Side stream A.
// ---------------------------------------------------------------------------
template <int FIN, int FOUT>
__global__ void gemm_kernel(const float* __restrict__ x,
                            const float* __restrict__ W,
                            float* __restrict__ h, int n) {
    constexpr int CH  = FOUT / 4;
    constexpr int CP  = CH / 2;
    constexpr int CH4 = CH / 4;
    __shared__ float sW[FIN * FOUT];
    __shared__ float sx[64][FIN + 1];

    int tid = threadIdx.x;
    for (int i = tid; i < FIN * FOUT / 4; i += 256)
        ((float4*)sW)[i] = ((const float4*)W)[i];

    int node0 = blockIdx.x * 64;
    for (int i = tid; i < 64 * FIN; i += 256) {
        int r = i / FIN, c = i % FIN;
        int nd = node0 + r;
        sx[r][c] = (nd < n) ? x[(size_t)nd * FIN + c] : 0.0f;
    }
    __syncthreads();

    int r = tid >> 2, t = tid & 3;
    int nd = node0 + r;

    unsigned long long acc2[CP];
#pragma unroll
    for (int i = 0; i < CP; i++) acc2[i] = 0ull;

#pragma unroll
    for (int k = 0; k < FIN; k++) {
        float xv = sx[r][k];
        unsigned xu = __float_as_uint(xv);
        unsigned long long xv2;
        asm("mov.b64 %0, {%1, %1};" : "=l"(xv2) : "r"(xu));
        const ulonglong2* wrow = (const ulonglong2*)(sW + k * FOUT) + t * CH4;
#pragma unroll
        for (int c = 0; c < CH4; c++) {
            ulonglong2 wv = wrow[c];
            asm("fma.rn.f32x2 %0, %1, %2, %0;" : "+l"(acc2[2 * c + 0]) : "l"(xv2), "l"(wv.x));
            asm("fma.rn.f32x2 %0, %1, %2, %0;" : "+l"(acc2[2 * c + 1]) : "l"(xv2), "l"(wv.y));
        }
    }

    if (nd < n) {
        float4* out = (float4*)(h + (size_t)nd * FOUT) + t * CH4;
#pragma unroll
        for (int c = 0; c < CH4; c++) {
            float a0, a1, a2, a3;
            asm("mov.b64 {%0, %1}, %2;" : "=f"(a0), "=f"(a1) : "l"(acc2[2 * c + 0]));
            asm("mov.b64 {%0, %1}, %2;" : "=f"(a2), "=f"(a3) : "l"(acc2[2 * c + 1]));
            out[c] = make_float4(a0, a1, a2, a3);
        }
    }
}

// ---------------------------------------------------------------------------
// scale1: h1[node,:] *= dinv1[node]  (so pull1 gathers need no deg loads)
// ---------------------------------------------------------------------------
__global__ void scale1_kernel(float* __restrict__ h1,
                              const int* __restrict__ deg1, int n) {
    int i = blockIdx.x * blockDim.x + threadIdx.x;   // over n*16 float4s
    if (i < n * 16) {
        int node = i >> 4;
        float di = rsqrtf((float)deg1[node] + 1.0f);
        float4 v = ((float4*)h1)[i];
        v.x *= di; v.y *= di; v.z *= di; v.w *= di;
        ((float4*)h1)[i] = v;
    }
}

// ---------------------------------------------------------------------------
// Fused pull(layer1) + gemm2. 16 nodes/block, TG=16. h1 prescaled.
// Pure-add gathers, int4 csr loads. Restores deg1[node]=0 inline.
// h2 written PRE-SCALED by dinv2 (reads deg2 -> needs cp23 done).
// ---------------------------------------------------------------------------
__global__ void pull1_gemm2_kernel(const float* __restrict__ h1,
                                   const float* __restrict__ b1,
                                   const float* __restrict__ W2,
                                   float* __restrict__ h2,
                                   int* __restrict__ deg1,
                                   const int* __restrict__ deg2, int n) {
    __shared__ float sx2[16][F1 + 1];
    __shared__ float sW2[F1 * F2];      // 8KB

    int tid = threadIdx.x;
    for (int i = tid; i < F1 * F2 / 4; i += 256)
        ((float4*)sW2)[i] = ((const float4*)W2)[i];

    int node = blockIdx.x * 16 + (tid >> 4);
    int f4   = tid & 15;

    if (node < n) {
        const float4* hp = (const float4*)h1;
        int dg = deg1[node];
        if (f4 == 0) deg1[node] = 0;     // sole remaining reader; restore invariant
        float di = rsqrtf((float)dg + 1.0f);
        float4 acc = hp[node * 16 + f4]; // self (prescaled)

        int idx = node << 6;
        int end = idx + dg;
        const int* __restrict__ csr = g_csr;

        for (; idx + 3 < end; idx += 4) {
            int4 s4 = *reinterpret_cast<const int4*>(csr + idx);
            float4 va = hp[s4.x * 16 + f4];
            float4 vb = hp[s4.y * 16 + f4];
            float4 vc = hp[s4.z * 16 + f4];
            float4 vd = hp[s4.w * 16 + f4];
            acc.x += (va.x + vb.x) + (vc.x + vd.x);
            acc.y += (va.y + vb.y) + (vc.y + vd.y);
            acc.z += (va.z + vb.z) + (vc.z + vd.z);
            acc.w += (va.w + vb.w) + (vc.w + vd.w);
        }
        for (; idx < end; idx++) {
            int sa = csr[idx];
            float4 va = hp[sa * 16 + f4];
            acc.x += va.x; acc.y += va.y; acc.z += va.z; acc.w += va.w;
        }

        float4 bb = *(const float4*)(b1 + f4 * 4);
        int r = tid >> 4;
        sx2[r][f4 * 4 + 0] = fmaxf(fmaf(di, acc.x, bb.x), 0.0f);
        sx2[r][f4 * 4 + 1] = fmaxf(fmaf(di, acc.y, bb.y), 0.0f);
        sx2[r][f4 * 4 + 2] = fmaxf(fmaf(di, acc.z, bb.z), 0.0f);
        sx2[r][f4 * 4 + 3] = fmaxf(fmaf(di, acc.w, bb.w), 0.0f);
    }
    __syncthreads();

    // gemm2: h2 = dinv2 * (x2 @ W2)
    int r  = tid >> 4;
    int j0 = tid & 15;
    int nd = blockIdx.x * 16 + r;
    if (nd < n) {
        float a0 = 0.0f, a1 = 0.0f;
#pragma unroll
        for (int k = 0; k < F1; k++) {
            float xv = sx2[r][k];
            a0 = fmaf(xv, sW2[k * F2 + j0],      a0);
            a1 = fmaf(xv, sW2[k * F2 + j0 + 16], a1);
        }
        float d2 = rsqrtf((float)deg2[nd] + 1.0f);
        h2[nd * F2 + j0]      = d2 * a0;
        h2[nd * F2 + j0 + 16] = d2 * a1;
    }
}

// ---------------------------------------------------------------------------
// Fused pull(layer2) + gemm3. 32 nodes/block, TG=8. h2 prescaled.
// Restores deg2[node]=0 inline.
// ---------------------------------------------------------------------------
__global__ void pull2_gemm3_kernel(const float* __restrict__ h2,
                                   const float* __restrict__ b2,
                                   const float* __restrict__ W3,
                                   float* __restrict__ h3,
                                   int* __restrict__ deg2,
                                   const int* __restrict__ deg3, int n) {
    __shared__ float sx3[32][F2 + 1];
    __shared__ float sW3[F2 * F3];      // 2KB

    int tid = threadIdx.x;
    for (int i = tid; i < F2 * F3 / 4; i += 256)
        ((float4*)sW3)[i] = ((const float4*)W3)[i];

    int node = blockIdx.x * 32 + (tid >> 3);
    int f4   = tid & 7;

    if (node < n) {
        const float4* hp = (const float4*)h2;
        int dg = deg2[node];
        if (f4 == 0) deg2[node] = 0;     // restore invariant
        float di = rsqrtf((float)dg + 1.0f);
        float4 acc = hp[node * 8 + f4];  // self (prescaled)

        int idx = (MAXN << 6) + (node << 6);
        int end = idx + dg;
        const int* __restrict__ csr = g_csr;

        for (; idx + 3 < end; idx += 4) {
            int4 s4 = *reinterpret_cast<const int4*>(csr + idx);
            float4 va = hp[s4.x * 8 + f4];
            float4 vb = hp[s4.y * 8 + f4];
            float4 vc = hp[s4.z * 8 + f4];
            float4 vd = hp[s4.w * 8 + f4];
            acc.x += (va.x + vb.x) + (vc.x + vd.x);
            acc.y += (va.y + vb.y) + (vc.y + vd.y);
            acc.z += (va.z + vb.z) + (vc.z + vd.z);
            acc.w += (va.w + vb.w) + (vc.w + vd.w);
        }
        for (; idx < end; idx++) {
            int sa = csr[idx];
            float4 va = hp[sa * 8 + f4];
            acc.x += va.x; acc.y += va.y; acc.z += va.z; acc.w += va.w;
        }

        float4 bb = *(const float4*)(b2 + f4 * 4);
        int r = tid >> 3;
        sx3[r][f4 * 4 + 0] = fmaxf(fmaf(di, acc.x, bb.x), 0.0f);
        sx3[r][f4 * 4 + 1] = fmaxf(fmaf(di, acc.y, bb.y), 0.0f);
        sx3[r][f4 * 4 + 2] = fmaxf(fmaf(di, acc.z, bb.z), 0.0f);
        sx3[r][f4 * 4 + 3] = fmaxf(fmaf(di, acc.w, bb.w), 0.0f);
    }
    __syncthreads();

    // gemm3: h3 = dinv3 * (x3 @ W3)
    int r  = tid >> 3;
    int j0 = tid & 7;
    int nd = blockIdx.x * 32 + r;
    if (nd < n) {
        float a0 = 0.0f, a1 = 0.0f;
#pragma unroll
        for (int k = 0; k < F2; k++) {
            float xv = sx3[r][k];
            a0 = fmaf(xv, sW3[k * F3 + j0],     a0);
            a1 = fmaf(xv, sW3[k * F3 + j0 + 8], a1);
        }
        float d3 = rsqrtf((float)deg3[nd] + 1.0f);
        h3[nd * F3 + j0]     = d3 * a0;
        h3[nd * F3 + j0 + 8] = d3 * a1;
    }
}

// ---------------------------------------------------------------------------
// Final pull (layer 3). h3 prescaled. Restores deg3[node]=0 inline.
// ---------------------------------------------------------------------------
__global__ void pull3_kernel(const float* __restrict__ h3,
                             const float* __restrict__ b3,
                             float* __restrict__ y,
                             int* __restrict__ deg3, int n) {
    constexpr int TG = F3 / 4;   // 4
    int t = blockIdx.x * blockDim.x + threadIdx.x;
    int node = t / TG;
    int f4   = t % TG;
    if (node >= n) return;

    const float4* hp = (const float4*)h3;
    int dg = deg3[node];
    if (f4 == 0) deg3[node] = 0;         // restore invariant
    float4 acc = hp[node * TG + f4];

    int idx = (2 * MAXN << 6) + (node << 6);
    int end = idx + dg;
    const int* __restrict__ csr = g_csr;

    for (; idx + 3 < end; idx += 4) {
        int4 s4 = *reinterpret_cast<const int4*>(csr + idx);
        float4 va = hp[s4.x * TG + f4];
        float4 vb = hp[s4.y * TG + f4];
        float4 vc = hp[s4.z * TG + f4];
        float4 vd = hp[s4.w * TG + f4];
        acc.x += (va.x + vb.x) + (vc.x + vd.x);
        acc.y += (va.y + vb.y) + (vc.y + vd.y);
        acc.z += (va.z + vb.z) + (vc.z + vd.z);
        acc.w += (va.w + vb.w) + (vc.w + vd.w);
    }
    for (; idx < end; idx++) {
        int sa = csr[idx];
        float4 va = hp[sa * TG + f4];
        acc.x += va.x; acc.y += va.y; acc.z += va.z; acc.w += va.w;
    }

    float di = rsqrtf((float)dg + 1.0f);
    float4 bb = *(const float4*)(b3 + f4 * 4);
    float4 o;
    o.x = fmaxf(fmaf(di, acc.x, bb.x), 0.0f);
    o.y = fmaxf(fmaf(di, acc.y, bb.y), 0.0f);
    o.z = fmaxf(fmaf(di, acc.z, bb.z), 0.0f);
    o.w = fmaxf(fmaf(di, acc.w, bb.w), 0.0f);
    ((float4*)y)[node * TG + f4] = o;
}

// ---------------------------------------------------------------------------
extern "C" void kernel_launch(void* const* d_in, const int* in_sizes, int n_in,
                              void* d_out, int out_size) {
    const float* features = (const float*)d_in[0];
    const int*   ei1      = (const int*)  d_in[1];
    const int*   ei2      = (const int*)  d_in[2];
    const int*   ei3      = (const int*)  d_in[3];
    const float* W1       = (const float*)d_in[4];
    const float* b1       = (const float*)d_in[5];
    const float* W2       = (const float*)d_in[6];
    const float* b2       = (const float*)d_in[7];
    const float* W3       = (const float*)d_in[8];
    const float* b3       = (const float*)d_in[9];
    float* out = (float*)d_out;

    int n  = in_sizes[0] / F0;       // 50000
    int e1 = in_sizes[1] / 2;
    int e2 = in_sizes[2] / 2;
    int e3 = in_sizes[3] / 2;

    const int* s1 = ei1;  const int* d1 = ei1 + e1;
    const int* s2 = ei2;  const int* d2 = ei2 + e2;
    const int* s3 = ei3;  const int* d3 = ei3 + e3;

    float* h1 = nullptr;  cudaGetSymbolAddress((void**)&h1, g_h1);
    float* h2 = nullptr;  cudaGetSymbolAddress((void**)&h2, g_h2);
    float* h3 = nullptr;  cudaGetSymbolAddress((void**)&h3, g_h3);
    int*   deg = nullptr; cudaGetSymbolAddress((void**)&deg, g_deg);

    static cudaStream_t sA = nullptr, sB = nullptr;
    static cudaEvent_t evF = nullptr, evA = nullptr, evB = nullptr;
    if (sA == nullptr) {
        cudaStreamCreateWithFlags(&sA, cudaStreamNonBlocking);
        cudaStreamCreateWithFlags(&sB, cudaStreamNonBlocking);
        cudaEventCreateWithFlags(&evF, cudaEventDisableTiming);
        cudaEventCreateWithFlags(&evA, cudaEventDisableTiming);
        cudaEventCreateWithFlags(&evB, cudaEventDisableTiming);
    }

    // Fork.
    cudaEventRecord(evF, 0);

    // Stream A: gemm1 (independent of graph preprocessing).
    cudaStreamWaitEvent(sA, evF, 0);
    gemm_kernel<F0, F1><<<(n + 63) / 64, 256, 0, sA>>>(features, W1, h1, n);
    cudaEventRecord(evA, sA);

    // Stream B: layers 2+3 fused count/place (deg zero on entry).
    cudaStreamWaitEvent(sB, evF, 0);
    {
        int th = (e2 + 3) / 4 + (e3 + 3) / 4 + 1;
        countplace23_kernel<<<(th + 255) / 256, 256, 0, sB>>>(s2, d2, e2, s3, d3, e3, n);
    }
    cudaEventRecord(evB, sB);

    // Main: layer-1 count/place (deg1 zero on entry).
    countplace_kernel<<<((e1 + 3) / 4 + 255) / 256, 256>>>(s1, d1, e1, 0);

    // scale1 needs h1 (evA) + deg1 (cp1, same stream).
    cudaStreamWaitEvent(0, evA, 0);
    scale1_kernel<<<(n * 16 + 255) / 256, 256>>>(h1, deg, n);

    // pull1's gemm2 epilogue reads deg2 -> wait cp23.
    cudaStreamWaitEvent(0, evB, 0);
    pull1_gemm2_kernel<<<(n + 15) / 16, 256>>>(h1, b1, W2, h2, deg, deg + n, n);

    pull2_gemm3_kernel<<<(n + 31) / 32, 256>>>(h2, b2, W3, h3, deg + n, deg + 2 * n, n);

    pull3_kernel<<<(n * (F3 / 4) + 255) / 256, 256>>>(h3, b3, out, deg + 2 * n, n);
}